// round 5
// baseline (speedup 1.0000x reference)
#include <cuda_runtime.h>
#include <cuda_fp16.h>
#include <cstdint>
#include <cstddef>

#define NT   512
#define NH   128
#define ND   32
#define CS   8          // cluster size = batches per cluster
#define NTHR 512
#define NB   64
#define BSTRIDE 65      // u32 words per B-tile row (pad: conflict-free LDS)

// ---------------- SMEM ----------------
struct __align__(16) SM {
    __half2  W0c[64 * NH];      // 32 KB: W0c[kp*128 + r] = (W0[r][2kp], W0[r][2kp+1])
    __half2  W1c[64 * NH];      // 32 KB
    uint32_t Bt[CS * BSTRIDE];  // B tile: 8 batches x 128 halfs (64 u32 used of 65)
    float    tsv[NT];
    float    b0v[NH], b1v[NH], lwv[NH];
    float    y[NH], ytmp[NH], h1[NH], h2[NH];
    float    kst[3][NH];
    float    derivAll[CS][ND + 1];   // padded: conflict-free by-batch reads
    float    red[4];
};

// ---------------- helpers ----------------
__device__ __forceinline__ uint32_t smem_u32(const void* p) {
    uint32_t a;
    asm("{ .reg .u64 t; cvta.to.shared.u64 t, %1; cvt.u32.u64 %0, t; }" : "=r"(a) : "l"(p));
    return a;
}
__device__ __forceinline__ uint32_t mapa_u32(uint32_t addr, uint32_t rank) {
    uint32_t r;
    asm("mapa.shared::cluster.u32 %0, %1, %2;" : "=r"(r) : "r"(addr), "r"(rank));
    return r;
}
__device__ __forceinline__ void st_cluster_u32(uint32_t addr, uint32_t v) {
    asm volatile("st.shared::cluster.u32 [%0], %1;" :: "r"(addr), "r"(v) : "memory");
}
__device__ __forceinline__ void st_cluster_f32(uint32_t addr, float v) {
    asm volatile("st.shared::cluster.f32 [%0], %1;" :: "r"(addr), "f"(v) : "memory");
}
#define CLUSTER_SYNC() do { \
    asm volatile("barrier.cluster.arrive.aligned;" ::: "memory"); \
    asm volatile("barrier.cluster.wait.aligned;"   ::: "memory"); } while (0)

__device__ __forceinline__ void mma16816(float* c, const uint32_t* a, uint32_t b0, uint32_t b1) {
    asm volatile("mma.sync.aligned.m16n8k16.row.col.f32.f16.f16.f32 "
                 "{%0,%1,%2,%3}, {%4,%5,%6,%7}, {%8,%9}, {%0,%1,%2,%3};"
                 : "+f"(c[0]), "+f"(c[1]), "+f"(c[2]), "+f"(c[3])
                 : "r"(a[0]), "r"(a[1]), "r"(a[2]), "r"(a[3]), "r"(b0), "r"(b1));
}
__device__ __forceinline__ float tanh_fast(float x) {
    float y; asm("tanh.approx.f32 %0, %1;" : "=f"(y) : "f"(x)); return y;
}
__device__ __forceinline__ float softplus_f(float x) {
    return fmaxf(x, 0.0f) + log1pf(expf(-fabsf(x)));
}
__device__ __forceinline__ uint32_t pack_h2(float a, float b) {
    __half2 h = __floats2half2_rn(a, b);
    return *reinterpret_cast<uint32_t*>(&h);
}

__global__ void __launch_bounds__(NTHR, 1) __cluster_dims__(CS, 1, 1)
cde_kernel(const float* __restrict__ ts,
           const float* __restrict__ cd, const float* __restrict__ cc,
           const float* __restrict__ cb, const float* __restrict__ ca,
           const float* __restrict__ iW0, const float* __restrict__ ib0,
           const float* __restrict__ iW1, const float* __restrict__ ib1,
           const float* __restrict__ iW2, const float* __restrict__ ib2,
           const float* __restrict__ fW0, const float* __restrict__ fb0,
           const float* __restrict__ fW1, const float* __restrict__ fb1,
           const float* __restrict__ fW2, const float* __restrict__ fb2,
           const float* __restrict__ lW, const float* __restrict__ lb,
           float* __restrict__ out)
{
    extern __shared__ char smraw[];
    SM* S = reinterpret_cast<SM*>(smraw);
    const int tid   = threadIdx.x;
    const int wid   = tid >> 5;
    const int lane  = tid & 31;
    const int gid   = lane >> 2;     // mma groupID (row / d)
    const int tig   = lane & 3;      // mma threadID-in-group (col / batch-pair)
    const int batch = blockIdx.x;
    const int rank  = batch & (CS - 1);
    const int cbat0 = batch & ~(CS - 1);

    const uint32_t btile_a = smem_u32(&S->Bt[0]);
    const uint32_t kst_a   = smem_u32(&S->kst[0][0]);

    // ---- load small weights / constants into SMEM ----
    for (int i = tid; i < NT; i += NTHR) S->tsv[i] = ts[(size_t)batch * NT + i];
    for (int i = tid; i < 64 * NH; i += NTHR) {
        int kp = i >> 7, r = i & 127;
        S->W0c[i] = __floats2half2_rn(fW0[r * NH + 2 * kp], fW0[r * NH + 2 * kp + 1]);
        S->W1c[i] = __floats2half2_rn(fW1[r * NH + 2 * kp], fW1[r * NH + 2 * kp + 1]);
    }
    if (tid < NH) { S->b0v[tid] = fb0[tid]; S->b1v[tid] = fb1[tid]; S->lwv[tid] = lW[tid]; }

    // ---- build register-resident A fragments of this warp's 32 W2 rows ----
    // warp wid owns global h = rank*16 + wid -> W2 rows [rank*512 + wid*32, +32)
    const int rowbase = rank * 512 + wid * 32;
    uint32_t areg[2][8][4];
    float    b2v[2][2];
    #pragma unroll
    for (int t = 0; t < 2; ++t) {
        int r0g = rowbase + t * 16 + gid;
        int r1g = r0g + 8;
        b2v[t][0] = fb2[r0g];
        b2v[t][1] = fb2[r1g];
        #pragma unroll
        for (int ks = 0; ks < 8; ++ks) {
            int c0 = ks * 16 + 2 * tig;
            int c1 = c0 + 8;
            const float* w0 = fW2 + (size_t)r0g * NH;
            const float* w1 = fW2 + (size_t)r1g * NH;
            areg[t][ks][0] = pack_h2(w0[c0], w0[c0 + 1]);
            areg[t][ks][1] = pack_h2(w1[c0], w1[c0 + 1]);
            areg[t][ks][2] = pack_h2(w0[c1], w0[c1 + 1]);
            areg[t][ks][3] = pack_h2(w1[c1], w1[c1 + 1]);
        }
    }
    __syncthreads();

    const size_t cbase = (size_t)batch * (NT - 1) * ND;

    // ---- initial MLP (fp32, exact) ----
    if (tid < ND) S->derivAll[0][tid] = ca[cbase + tid];
    __syncthreads();
    if (tid < NH) {
        float a = ib0[tid];
        #pragma unroll
        for (int k = 0; k < ND; ++k) a = fmaf(iW0[tid * ND + k], S->derivAll[0][k], a);
        S->h1[tid] = fmaxf(a, 0.0f);
    }
    __syncthreads();
    if (tid < NH) {
        float a = ib1[tid];
        for (int k = 0; k < NH; ++k) a = fmaf(iW1[tid * NH + k], S->h1[k], a);
        S->h2[tid] = fmaxf(a, 0.0f);
    }
    __syncthreads();
    if (tid < NH) {
        float a = ib2[tid];
        for (int k = 0; k < NH; ++k) a = fmaf(iW2[tid * NH + k], S->h2[k], a);
        S->y[tid] = a;
    }

    const float dtv = S->tsv[1] - S->tsv[0];
    float t0 = S->tsv[0];
    const float lbv = lb[0];

    // B broadcast addressing: thread -> (peer = tid>>6, word j = tid&63) of row `rank`
    const int wpeer = tid >> 6;
    const int wj    = tid & 63;
    const uint32_t b_remote = mapa_u32(btile_a + (uint32_t)((rank * BSTRIDE + wj) << 2),
                                       (uint32_t)wpeer);
    // k-scatter addressing (lanes 0..3 only meaningful): batches 2*tig, 2*tig+1
    const int hidx = rank * 16 + wid;
    const uint32_t kst_e = mapa_u32(kst_a + (uint32_t)(hidx << 2), (uint32_t)(2 * tig));
    const uint32_t kst_o = mapa_u32(kst_a + (uint32_t)(hidx << 2), (uint32_t)(2 * tig + 1));

    const uint32_t* BtW = S->Bt;

    CLUSTER_SYNC();

    for (int s = 0; s < NT; ++s) {
        #pragma unroll 1
        for (int stg = 0; stg < 3; ++stg) {
            __syncthreads();   // y/ytmp (and prior-stage Bt reuse) settled
            const float te = (stg == 0) ? t0 : ((stg == 1) ? (t0 + 0.5f * dtv) : (t0 + 0.75f * dtv));
            const float* yin = (stg == 0) ? S->y : S->ytmp;

            // --- layer 1 (warps 0-7) + spline derivs for all 8 batches (warps 8-15) ---
            if (tid < 256) {
                int row = tid >> 1, hh = tid & 1;
                const __half2* Wc = S->W0c + (hh << 5) * NH;
                float acc = 0.0f;
                #pragma unroll 8
                for (int kp = 0; kp < 32; ++kp) {
                    float2 w = __half22float2(Wc[kp * NH + row]);
                    float2 yv = *reinterpret_cast<const float2*>(&yin[(hh << 6) + (kp << 1)]);
                    acc = fmaf(w.x, yv.x, fmaf(w.y, yv.y, acc));
                }
                acc += __shfl_xor_sync(0xffffffffu, acc, 1);
                if (hh == 0) S->h1[row] = softplus_f(acc + S->b0v[row]);
            } else if (wid >= 8) {
                int bb = wid - 8;
                int idx = 0;
                #pragma unroll
                for (int stp = 256; stp > 0; stp >>= 1) {
                    int c2 = idx + stp;
                    if (c2 < NT && S->tsv[c2] <= te) idx = c2;
                }
                if (idx > NT - 2) idx = NT - 2;
                float frac = te - S->tsv[idx];
                size_t off = (size_t)(cbat0 + bb) * (NT - 1) * ND + (size_t)idx * ND + lane;
                float vb = cb[off], vc = cc[off], vd = cd[off];
                S->derivAll[bb][lane] = vb + frac * (2.0f * vc + frac * 3.0f * vd);
            }
            __syncthreads();

            // --- layer 2 (warps 0-7) ---
            if (tid < 256) {
                int row = tid >> 1, hh = tid & 1;
                const __half2* Wc = S->W1c + (hh << 5) * NH;
                float acc = 0.0f;
                #pragma unroll 8
                for (int kp = 0; kp < 32; ++kp) {
                    float2 w = __half22float2(Wc[kp * NH + row]);
                    float2 yv = *reinterpret_cast<const float2*>(&S->h1[(hh << 6) + (kp << 1)]);
                    acc = fmaf(w.x, yv.x, fmaf(w.y, yv.y, acc));
                }
                acc += __shfl_xor_sync(0xffffffffu, acc, 1);
                if (hh == 0) S->h2[row] = softplus_f(acc + S->b1v[row]);
            }
            __syncthreads();

            // --- broadcast h2 (fp16) into row `rank` of every cluster CTA's B tile ---
            {
                float2 hv = *reinterpret_cast<const float2*>(&S->h2[wj << 1]);
                st_cluster_u32(b_remote, pack_h2(hv.x, hv.y));
            }
            CLUSTER_SYNC();   // all 8 rows of B present everywhere

            // --- HMMA: D[32 rows(d) x 8 batches] per warp, A in registers ---
            {
                float c0[4] = {0.f, 0.f, 0.f, 0.f};
                float c1[4] = {0.f, 0.f, 0.f, 0.f};
                #pragma unroll
                for (int ks = 0; ks < 8; ++ks) {
                    uint32_t b0 = BtW[gid * BSTRIDE + ks * 8 + tig];
                    uint32_t b1 = BtW[gid * BSTRIDE + ks * 8 + tig + 4];
                    mma16816(c0, areg[0][ks], b0, b1);
                    mma16816(c1, areg[1][ks], b0, b1);
                }
                // epilogue: tanh + deriv contraction; d = t*16 + gid (+8), col batch = 2*tig (+1)
                const float* dvE = S->derivAll[2 * tig];
                const float* dvO = S->derivAll[2 * tig + 1];
                float pe, po;
                {
                    float z00 = tanh_fast(c0[0] + b2v[0][0]);
                    float z02 = tanh_fast(c0[2] + b2v[0][1]);
                    float z10 = tanh_fast(c1[0] + b2v[1][0]);
                    float z12 = tanh_fast(c1[2] + b2v[1][1]);
                    pe = z00 * dvE[gid] + z02 * dvE[gid + 8]
                       + z10 * dvE[gid + 16] + z12 * dvE[gid + 24];
                    float z01 = tanh_fast(c0[1] + b2v[0][0]);
                    float z03 = tanh_fast(c0[3] + b2v[0][1]);
                    float z11 = tanh_fast(c1[1] + b2v[1][0]);
                    float z13 = tanh_fast(c1[3] + b2v[1][1]);
                    po = z01 * dvO[gid] + z03 * dvO[gid + 8]
                       + z11 * dvO[gid + 16] + z13 * dvO[gid + 24];
                }
                #pragma unroll
                for (int m = 4; m < 32; m <<= 1) {
                    pe += __shfl_xor_sync(0xffffffffu, pe, m);
                    po += __shfl_xor_sync(0xffffffffu, po, m);
                }
                if (lane < 4) {
                    uint32_t soff = (uint32_t)(stg * NH) << 2;
                    st_cluster_f32(kst_e + soff, pe);
                    st_cluster_f32(kst_o + soff, po);
                }
            }
            CLUSTER_SYNC();   // all k partials delivered to owners

            // --- stage update ---
            if (tid < NH) {
                float kv = S->kst[stg][tid] * dtv;
                S->kst[stg][tid] = kv;
                if (stg == 0)      S->ytmp[tid] = S->y[tid] + 0.5f  * kv;
                else if (stg == 1) S->ytmp[tid] = S->y[tid] + 0.75f * kv;
                else {
                    float yn = (2.0f / 9.0f) * S->kst[0][tid]
                             + (1.0f / 3.0f) * S->kst[1][tid]
                             + (4.0f / 9.0f) * kv;
                    yn = yn * dtv + S->y[tid];
                    S->y[tid] = yn;
                    float part = yn * S->lwv[tid];
                    #pragma unroll
                    for (int o = 16; o > 0; o >>= 1)
                        part += __shfl_down_sync(0xffffffffu, part, o);
                    if (lane == 0) S->red[wid] = part;
                }
            }
        }
        __syncthreads();
        if (tid == 0) {
            float v = S->red[0] + S->red[1] + S->red[2] + S->red[3] + lbv;
            out[(size_t)batch * NT + s] = 1.0f / (1.0f + expf(-v));
        }
        t0 += dtv;   // exact fp32 carry, matches the JAX scan
    }
    CLUSTER_SYNC();
}

extern "C" void kernel_launch(void* const* d_in, const int* in_sizes, int n_in,
                              void* d_out, int out_size) {
    const float* ts  = (const float*)d_in[0];
    const float* cd  = (const float*)d_in[1];
    const float* cc  = (const float*)d_in[2];
    const float* cb  = (const float*)d_in[3];
    const float* ca  = (const float*)d_in[4];
    const float* iW0 = (const float*)d_in[5];
    const float* ib0 = (const float*)d_in[6];
    const float* iW1 = (const float*)d_in[7];
    const float* ib1 = (const float*)d_in[8];
    const float* iW2 = (const float*)d_in[9];
    const float* ib2 = (const float*)d_in[10];
    const float* fW0 = (const float*)d_in[11];
    const float* fb0 = (const float*)d_in[12];
    const float* fW1 = (const float*)d_in[13];
    const float* fb1 = (const float*)d_in[14];
    const float* fW2 = (const float*)d_in[15];
    const float* fb2 = (const float*)d_in[16];
    const float* lW  = (const float*)d_in[17];
    const float* lb  = (const float*)d_in[18];
    float* o = (float*)d_out;

    cudaFuncSetAttribute(cde_kernel, cudaFuncAttributeMaxDynamicSharedMemorySize,
                         (int)sizeof(SM));
    cde_kernel<<<NB, NTHR, sizeof(SM)>>>(ts, cd, cc, cb, ca,
                                         iW0, ib0, iW1, ib1, iW2, ib2,
                                         fW0, fb0, fW1, fb1, fW2, fb2,
                                         lW, lb, o);
}

// round 6
// speedup vs baseline: 1.6517x; 1.6517x over previous
#include <cuda_runtime.h>
#include <cuda_fp16.h>
#include <cstdint>
#include <cstddef>

#define NT 512
#define NH 128
#define ND 32
#define CS 8
#define NTHR 512
#define NB 64
#define BSTR 68
#define DSTR 34

__device__ float g_deriv[(size_t)NT * 3 * NB * ND];   // 12 MB static scratch

__global__ void prep_deriv(const float* __restrict__ ts, const float* __restrict__ cd,
                           const float* __restrict__ cc, const float* __restrict__ cb) {
    int b = blockIdx.x, chunk = blockIdx.y;
    int sl = threadIdx.x >> 5, d = threadIdx.x & 31;
    int s = chunk * 16 + sl;
    __shared__ float tsv[NT];
    for (int i = threadIdx.x; i < NT; i += 512) tsv[i] = ts[(size_t)b * NT + i];
    __syncthreads();
    float dt = tsv[1] - tsv[0], t0 = tsv[0];
    for (int i = 0; i < s; ++i) t0 += dt;          // exact fp32 carry, matches scan
    for (int stg = 0; stg < 3; ++stg) {
        float te = (stg == 0) ? t0 : ((stg == 1) ? t0 + 0.5f * dt : t0 + 0.75f * dt);
        int idx = 0;
        #pragma unroll
        for (int stp = 256; stp > 0; stp >>= 1) {
            int c2 = idx + stp;
            if (c2 < NT && tsv[c2] <= te) idx = c2;
        }
        if (idx > NT - 2) idx = NT - 2;
        float fr = te - tsv[idx];
        size_t off = ((size_t)b * (NT - 1) + idx) * ND + d;
        g_deriv[(((size_t)s * 3 + stg) * NB + b) * ND + d] =
            cb[off] + fr * (2.0f * cc[off] + fr * 3.0f * cd[off]);
    }
}

struct __align__(16) SM {
    uint32_t W0q[4 * NH * 20];     // 40960 B  [kq][row][16 words + pad4]
    uint32_t W1q[4 * NH * 20];     // 40960 B
    uint32_t Bt[CS * BSTR];        //  2176 B  [batch][64 words + pad]
    float    drv[2][3][CS * DSTR]; //  6528 B  double-buffered derivs (stride 34)
    float    y[NH], ytmp[NH], h1[NH];
    float    kst[3][NH];
    float    b0v[NH], b1v[NH], lwv[NH];
    float    red[4];
    float    a0s[ND];
    unsigned long long bbar, kbar;
};

__device__ __forceinline__ uint32_t smem_u32(const void* p) {
    uint32_t a;
    asm("{ .reg .u64 t; cvta.to.shared.u64 t, %1; cvt.u32.u64 %0, t; }" : "=r"(a) : "l"(p));
    return a;
}
__device__ __forceinline__ uint32_t mapa_u32(uint32_t addr, uint32_t rank) {
    uint32_t r;
    asm("mapa.shared::cluster.u32 %0, %1, %2;" : "=r"(r) : "r"(addr), "r"(rank));
    return r;
}
__device__ __forceinline__ void st_async32(uint32_t ra, uint32_t v, uint32_t rb) {
    asm volatile("st.async.shared::cluster.mbarrier::complete_tx::bytes.b32 [%0], %1, [%2];"
                 :: "r"(ra), "r"(v), "r"(rb) : "memory");
}
__device__ __forceinline__ void mbar_init(uint32_t mb, uint32_t cnt) {
    asm volatile("mbarrier.init.shared.b64 [%0], %1;" :: "r"(mb), "r"(cnt) : "memory");
}
__device__ __forceinline__ void mbar_expect(uint32_t mb, uint32_t tx) {
    asm volatile("mbarrier.arrive.expect_tx.shared::cta.b64 _, [%0], %1;"
                 :: "r"(mb), "r"(tx) : "memory");
}
__device__ __forceinline__ void mbar_wait(uint32_t mb, uint32_t parity) {
    uint32_t done;
    asm volatile("{\n\t.reg .pred p;\n\t"
                 "mbarrier.try_wait.parity.acquire.cluster.shared::cta.b64 p, [%1], %2;\n\t"
                 "selp.b32 %0, 1, 0, p;\n\t}" : "=r"(done) : "r"(mb), "r"(parity) : "memory");
    if (!done) {
        asm volatile("{\n\t.reg .pred P1;\n\t"
                     "WL_%=:\n\t"
                     "mbarrier.try_wait.parity.acquire.cluster.shared::cta.b64 P1, [%0], %1, 0x989680;\n\t"
                     "@P1 bra.uni WD_%=;\n\t"
                     "bra.uni WL_%=;\n\t"
                     "WD_%=:\n\t}" :: "r"(mb), "r"(parity) : "memory");
    }
}
#define CLUSTER_SYNC() do { \
    asm volatile("barrier.cluster.arrive.aligned;" ::: "memory"); \
    asm volatile("barrier.cluster.wait.aligned;"   ::: "memory"); } while (0)

__device__ __forceinline__ void mma16816(float* c, const uint32_t* a, uint32_t b0, uint32_t b1) {
    asm volatile("mma.sync.aligned.m16n8k16.row.col.f32.f16.f16.f32 "
                 "{%0,%1,%2,%3}, {%4,%5,%6,%7}, {%8,%9}, {%0,%1,%2,%3};"
                 : "+f"(c[0]), "+f"(c[1]), "+f"(c[2]), "+f"(c[3])
                 : "r"(a[0]), "r"(a[1]), "r"(a[2]), "r"(a[3]), "r"(b0), "r"(b1));
}
__device__ __forceinline__ float tanh_fast(float x) {
    float y; asm("tanh.approx.f32 %0, %1;" : "=f"(y) : "f"(x)); return y;
}
__device__ __forceinline__ float softplus_f(float x) {
    return fmaxf(x, 0.0f) + log1pf(expf(-fabsf(x)));
}
__device__ __forceinline__ uint32_t pack_h2(float a, float b) {
    __half2 h = __floats2half2_rn(a, b);
    return *reinterpret_cast<uint32_t*>(&h);
}
__device__ __forceinline__ float2 h2f(uint32_t u) {
    __half2 h = *reinterpret_cast<__half2*>(&u);
    return __half22float2(h);
}

__global__ void __launch_bounds__(NTHR, 1) __cluster_dims__(CS, 1, 1)
cde_kernel(const float* __restrict__ ts, const float* __restrict__ ca,
           const float* __restrict__ iW0, const float* __restrict__ ib0,
           const float* __restrict__ iW1, const float* __restrict__ ib1,
           const float* __restrict__ iW2, const float* __restrict__ ib2,
           const float* __restrict__ fW0, const float* __restrict__ fb0,
           const float* __restrict__ fW1, const float* __restrict__ fb1,
           const float* __restrict__ fW2, const float* __restrict__ fb2,
           const float* __restrict__ lW, const float* __restrict__ lb,
           float* __restrict__ out)
{
    extern __shared__ char smraw[];
    SM* S = reinterpret_cast<SM*>(smraw);
    const int tid = threadIdx.x, wid = tid >> 5, lane = tid & 31;
    const int gid = lane >> 2, tig = lane & 3;
    const int batch = blockIdx.x;
    const int rank = batch & (CS - 1), cbat0 = batch & ~(CS - 1);

    const uint32_t bt_a   = smem_u32(&S->Bt[0]);
    const uint32_t kst_a  = smem_u32(&S->kst[0][0]);
    const uint32_t bbar_a = smem_u32(&S->bbar);
    const uint32_t kbar_a = smem_u32(&S->kbar);

    if (tid == 0) {
        mbar_init(bbar_a, 1);
        mbar_init(kbar_a, 1);
        mbar_expect(bbar_a, 2048);
        mbar_expect(kbar_a, 512);
        asm volatile("fence.mbarrier_init.release.cluster;" ::: "memory");
    }

    // ---- weights to SMEM (conflict-free padded layout) ----
    for (int i = tid; i < NH * 64; i += NTHR) {
        int row = i >> 6, w = i & 63;
        int kq = w >> 4, ii = w & 15;
        S->W0q[(kq * NH + row) * 20 + ii] = pack_h2(fW0[row * NH + 2 * w], fW0[row * NH + 2 * w + 1]);
        S->W1q[(kq * NH + row) * 20 + ii] = pack_h2(fW1[row * NH + 2 * w], fW1[row * NH + 2 * w + 1]);
    }
    if (tid < NH) { S->b0v[tid] = fb0[tid]; S->b1v[tid] = fb1[tid]; S->lwv[tid] = lW[tid]; }

    // ---- register-resident W2 fragments: warp owns h = rank*16+wid -> 32 rows ----
    const int rowbase = rank * 512 + wid * 32;
    uint32_t areg[2][8][4];
    float b2v[2][2];
    #pragma unroll
    for (int t = 0; t < 2; ++t) {
        int r0g = rowbase + t * 16 + gid, r1g = r0g + 8;
        b2v[t][0] = fb2[r0g]; b2v[t][1] = fb2[r1g];
        #pragma unroll
        for (int ks = 0; ks < 8; ++ks) {
            int c0 = ks * 16 + 2 * tig;
            const float* w0 = fW2 + (size_t)r0g * NH;
            const float* w1 = fW2 + (size_t)r1g * NH;
            areg[t][ks][0] = pack_h2(w0[c0], w0[c0 + 1]);
            areg[t][ks][1] = pack_h2(w1[c0], w1[c0 + 1]);
            areg[t][ks][2] = pack_h2(w0[c0 + 8], w0[c0 + 9]);
            areg[t][ks][3] = pack_h2(w1[c0 + 8], w1[c0 + 9]);
        }
    }
    __syncthreads();

    // ---- initial MLP (fp32, exact, once) ----
    if (tid < ND) S->a0s[tid] = ca[(size_t)batch * (NT - 1) * ND + tid];
    __syncthreads();
    if (tid < NH) {
        float a = ib0[tid];
        #pragma unroll
        for (int k = 0; k < ND; ++k) a = fmaf(iW0[tid * ND + k], S->a0s[k], a);
        S->h1[tid] = fmaxf(a, 0.0f);
    }
    __syncthreads();
    if (tid < NH) {
        float a = ib1[tid];
        for (int k = 0; k < NH; ++k) a = fmaf(iW1[tid * NH + k], S->h1[k], a);
        S->ytmp[tid] = fmaxf(a, 0.0f);
    }
    __syncthreads();
    if (tid < NH) {
        float a = ib2[tid];
        for (int k = 0; k < NH; ++k) a = fmaf(iW2[tid * NH + k], S->ytmp[k], a);
        S->y[tid] = a;
    }

    // ---- prologue: derivs for s=0 into buf 0 ----
    if (tid < 192) {
        int stgp = tid >> 6, r = tid & 63, b = r >> 3, seg = r & 7;
        float4 v = *(const float4*)&g_deriv[(((size_t)0 * 3 + stgp) * NB + cbat0 + b) * ND + seg * 4];
        float* dp = &S->drv[0][stgp][b * DSTR + seg * 4];
        *(float2*)dp = make_float2(v.x, v.y);
        *(float2*)(dp + 2) = make_float2(v.z, v.w);
    }
    __syncthreads();
    CLUSTER_SYNC();

    const float dtv = ts[(size_t)batch * NT + 1] - ts[(size_t)batch * NT];
    const float lbv = lb[0];
    uint32_t bpar = 0, kpar = 0;

    const int lrow = wid * 8 + (lane & 7);   // layer row
    const int kq = lane >> 3;
    const uint32_t* w0base = S->W0q + (kq * NH + lrow) * 20;
    const uint32_t* w1base = S->W1q + (kq * NH + lrow) * 20;

    // B send: lane -> peer (lane>>2), word wid*4+(lane&3) of row `rank`
    const uint32_t b_rem   = mapa_u32(bt_a + (uint32_t)((rank * BSTR + wid * 4 + (lane & 3)) << 2),
                                      (uint32_t)(lane >> 2));
    const uint32_t bbar_rem = mapa_u32(bbar_a, (uint32_t)(lane >> 2));
    // k scatter (lanes 0-3): peers 2*tig, 2*tig+1, slot h = rank*16+wid
    const int hidx = rank * 16 + wid;
    const uint32_t kst_e  = mapa_u32(kst_a + (uint32_t)(hidx << 2), (uint32_t)(2 * tig));
    const uint32_t kst_o  = mapa_u32(kst_a + (uint32_t)(hidx << 2), (uint32_t)(2 * tig + 1));
    const uint32_t kbar_e = mapa_u32(kbar_a, (uint32_t)(2 * tig));
    const uint32_t kbar_o = mapa_u32(kbar_a, (uint32_t)(2 * tig + 1));

    for (int s = 0; s < NT; ++s) {
        const float* dbuf0 = S->drv[s & 1][0];
        #pragma unroll 1
        for (int stg = 0; stg < 3; ++stg) {
            __syncthreads();
            const float* yin = (stg == 0) ? S->y : S->ytmp;

            // ---- layer 1 (all threads) + stage0 extras ----
            float4 pf;
            if (stg == 0) {
                if (tid == 0 && s > 0) {
                    float v = S->red[0] + S->red[1] + S->red[2] + S->red[3] + lbv;
                    out[(size_t)batch * NT + s - 1] = 1.0f / (1.0f + expf(-v));
                }
                if (tid < 192) {
                    int s1 = (s + 1 < NT) ? s + 1 : NT - 1;
                    int stgp = tid >> 6, r = tid & 63, b = r >> 3, seg = r & 7;
                    pf = *(const float4*)&g_deriv[(((size_t)s1 * 3 + stgp) * NB + cbat0 + b) * ND + seg * 4];
                }
            }
            {
                float acc = 0.0f;
                #pragma unroll
                for (int i = 0; i < 4; ++i) {
                    uint4 w = *(const uint4*)(w0base + i * 4);
                    float4 ya = *(const float4*)&yin[kq * 32 + i * 8];
                    float4 yb = *(const float4*)&yin[kq * 32 + i * 8 + 4];
                    float2 f0 = h2f(w.x), f1 = h2f(w.y), f2 = h2f(w.z), f3 = h2f(w.w);
                    acc = fmaf(f0.x, ya.x, acc); acc = fmaf(f0.y, ya.y, acc);
                    acc = fmaf(f1.x, ya.z, acc); acc = fmaf(f1.y, ya.w, acc);
                    acc = fmaf(f2.x, yb.x, acc); acc = fmaf(f2.y, yb.y, acc);
                    acc = fmaf(f3.x, yb.z, acc); acc = fmaf(f3.y, yb.w, acc);
                }
                acc += __shfl_xor_sync(0xffffffffu, acc, 8);
                acc += __shfl_xor_sync(0xffffffffu, acc, 16);
                if (lane < 8) S->h1[lrow] = softplus_f(acc + S->b0v[lrow]);
            }
            if (stg == 0 && tid < 192) {
                int stgp = tid >> 6, r = tid & 63, b = r >> 3, seg = r & 7;
                float* dp = &S->drv[(s + 1) & 1][stgp][b * DSTR + seg * 4];
                *(float2*)dp = make_float2(pf.x, pf.y);
                *(float2*)(dp + 2) = make_float2(pf.z, pf.w);
            }
            __syncthreads();

            // ---- layer 2 (all threads) -> h2 value on every lane for its row ----
            float val;
            {
                float acc = 0.0f;
                #pragma unroll
                for (int i = 0; i < 4; ++i) {
                    uint4 w = *(const uint4*)(w1base + i * 4);
                    float4 ya = *(const float4*)&S->h1[kq * 32 + i * 8];
                    float4 yb = *(const float4*)&S->h1[kq * 32 + i * 8 + 4];
                    float2 f0 = h2f(w.x), f1 = h2f(w.y), f2 = h2f(w.z), f3 = h2f(w.w);
                    acc = fmaf(f0.x, ya.x, acc); acc = fmaf(f0.y, ya.y, acc);
                    acc = fmaf(f1.x, ya.z, acc); acc = fmaf(f1.y, ya.w, acc);
                    acc = fmaf(f2.x, yb.x, acc); acc = fmaf(f2.y, yb.y, acc);
                    acc = fmaf(f3.x, yb.z, acc); acc = fmaf(f3.y, yb.w, acc);
                }
                acc += __shfl_xor_sync(0xffffffffu, acc, 8);
                acc += __shfl_xor_sync(0xffffffffu, acc, 16);
                val = softplus_f(acc + S->b1v[lrow]);
            }
            // ---- broadcast h2 (fp16) to all peers' B tiles via st.async ----
            {
                float lo = __shfl_sync(0xffffffffu, val, 2 * (lane & 3));
                float hi = __shfl_sync(0xffffffffu, val, 2 * (lane & 3) + 1);
                st_async32(b_rem, pack_h2(lo, hi), bbar_rem);
            }
            mbar_wait(bbar_a, bpar); bpar ^= 1;
            if (tid == 0) mbar_expect(bbar_a, 2048);

            // ---- HMMA + epilogue ----
            {
                float c0[4] = {0.f, 0.f, 0.f, 0.f};
                float c1[4] = {0.f, 0.f, 0.f, 0.f};
                const uint32_t* BtW = S->Bt;
                #pragma unroll
                for (int ks = 0; ks < 8; ++ks) {
                    uint32_t b0 = BtW[gid * BSTR + ks * 8 + tig];
                    uint32_t b1 = BtW[gid * BSTR + ks * 8 + tig + 4];
                    mma16816(c0, areg[0][ks], b0, b1);
                    mma16816(c1, areg[1][ks], b0, b1);
                }
                const float* dvE = dbuf0 + (size_t)stg * (CS * DSTR) + (2 * tig) * DSTR;
                const float* dvO = dvE + DSTR;
                float pe, po;
                {
                    float z00 = tanh_fast(c0[0] + b2v[0][0]);
                    float z02 = tanh_fast(c0[2] + b2v[0][1]);
                    float z10 = tanh_fast(c1[0] + b2v[1][0]);
                    float z12 = tanh_fast(c1[2] + b2v[1][1]);
                    pe = z00 * dvE[gid] + z02 * dvE[gid + 8] + z10 * dvE[gid + 16] + z12 * dvE[gid + 24];
                    float z01 = tanh_fast(c0[1] + b2v[0][0]);
                    float z03 = tanh_fast(c0[3] + b2v[0][1]);
                    float z11 = tanh_fast(c1[1] + b2v[1][0]);
                    float z13 = tanh_fast(c1[3] + b2v[1][1]);
                    po = z01 * dvO[gid] + z03 * dvO[gid + 8] + z11 * dvO[gid + 16] + z13 * dvO[gid + 24];
                }
                #pragma unroll
                for (int m = 4; m < 32; m <<= 1) {
                    pe += __shfl_xor_sync(0xffffffffu, pe, m);
                    po += __shfl_xor_sync(0xffffffffu, po, m);
                }
                if (lane < 4) {
                    uint32_t soff = (uint32_t)(stg * NH) << 2;
                    st_async32(kst_e + soff, __float_as_uint(pe), kbar_e);
                    st_async32(kst_o + soff, __float_as_uint(po), kbar_o);
                }
            }

            // ---- k wait + stage update (updater half only) ----
            if (tid < NH) {
                mbar_wait(kbar_a, kpar);
                if (tid == 0) mbar_expect(kbar_a, 512);
                float kv = S->kst[stg][tid] * dtv;
                S->kst[stg][tid] = kv;
                if (stg == 0)      S->ytmp[tid] = S->y[tid] + 0.5f  * kv;
                else if (stg == 1) S->ytmp[tid] = S->y[tid] + 0.75f * kv;
                else {
                    float yn = (2.0f / 9.0f) * S->kst[0][tid]
                             + (1.0f / 3.0f) * S->kst[1][tid]
                             + (4.0f / 9.0f) * kv;
                    yn = yn * dtv + S->y[tid];
                    S->y[tid] = yn;
                    float part = yn * S->lwv[tid];
                    #pragma unroll
                    for (int o = 16; o > 0; o >>= 1)
                        part += __shfl_down_sync(0xffffffffu, part, o);
                    if (lane == 0) S->red[wid] = part;
                }
            }
            kpar ^= 1;
        }
    }
    __syncthreads();
    if (tid == 0) {
        float v = S->red[0] + S->red[1] + S->red[2] + S->red[3] + lbv;
        out[(size_t)batch * NT + NT - 1] = 1.0f / (1.0f + expf(-v));
    }
    CLUSTER_SYNC();
}

extern "C" void kernel_launch(void* const* d_in, const int* in_sizes, int n_in,
                              void* d_out, int out_size) {
    const float* ts  = (const float*)d_in[0];
    const float* cd  = (const float*)d_in[1];
    const float* cc  = (const float*)d_in[2];
    const float* cb  = (const float*)d_in[3];
    const float* ca  = (const float*)d_in[4];
    const float* iW0 = (const float*)d_in[5];
    const float* ib0 = (const float*)d_in[6];
    const float* iW1 = (const float*)d_in[7];
    const float* ib1 = (const float*)d_in[8];
    const float* iW2 = (const float*)d_in[9];
    const float* ib2 = (const float*)d_in[10];
    const float* fW0 = (const float*)d_in[11];
    const float* fb0 = (const float*)d_in[12];
    const float* fW1 = (const float*)d_in[13];
    const float* fb1 = (const float*)d_in[14];
    const float* fW2 = (const float*)d_in[15];
    const float* fb2 = (const float*)d_in[16];
    const float* lW  = (const float*)d_in[17];
    const float* lb  = (const float*)d_in[18];
    float* o = (float*)d_out;

    prep_deriv<<<dim3(NB, NT / 16), 512>>>(ts, cd, cc, cb);
    cudaFuncSetAttribute(cde_kernel, cudaFuncAttributeMaxDynamicSharedMemorySize,
                         (int)sizeof(SM));
    cde_kernel<<<NB, NTHR, sizeof(SM)>>>(ts, ca,
                                         iW0, ib0, iW1, ib1, iW2, ib2,
                                         fW0, fb0, fW1, fb1, fW2, fb2,
                                         lW, lb, o);
}